// round 1
// baseline (speedup 1.0000x reference)
#include <cuda_runtime.h>

#define BATCH 2
#define NCAM  6
#define CH    128
#define IH    16
#define IW    44
#define ND    64
#define HW    (IH*IW)                 // 704
#define NPTS  (NCAM*ND*IH*IW)         // 270336 geometry points (batch-independent)
#define BEV_H 256
#define BEV_W 256
#define NBIN  (BEV_H*BEV_W)           // 65536

// Static scratch (allocation-free per harness rules)
__device__ float g_scratch[(size_t)BATCH*NBIN*CH];   // 64 MB, layout (b, bin, c)
__device__ float g_cnt[NBIN];
__device__ float g_featT[(size_t)BATCH*NCAM*HW*CH];  // feat in channel-last layout
__device__ float g_Kinv[NCAM*9];
__device__ float g_Rm[NCAM*9];
__device__ float g_tv[NCAM*3];

// ---------------------------------------------------------------------------
// Per-camera setup: K' = intrinsics row-scaled by rs, invert 3x3, pull R|t.
// Geometry identical across batch (inputs are broadcast), so use b=0.
// ---------------------------------------------------------------------------
__global__ void setup_kernel(const float* __restrict__ intr,
                             const float* __restrict__ extr,
                             const int* __restrict__ pimg_h,
                             const int* __restrict__ pimg_w) {
    int n = threadIdx.x;
    if (n >= NCAM) return;
    float img_h = (float)pimg_h[0], img_w = (float)pimg_w[0];
    float sx = (float)IW / (img_w / 16.0f);
    float sy = (float)IH / (img_h / 16.0f);
    float rs0 = 16.0f / sx, rs1 = 16.0f / sy, rs2 = 1.0f;

    const float* Kp = intr + n*9;   // b = 0
    float a = Kp[0]*rs0, b = Kp[1]*rs0, c = Kp[2]*rs0;
    float d = Kp[3]*rs1, e = Kp[4]*rs1, f = Kp[5]*rs1;
    float g = Kp[6]*rs2, h = Kp[7]*rs2, i = Kp[8]*rs2;
    float A  = e*i - f*h;
    float Bc = -(d*i - f*g);
    float Cc = d*h - e*g;
    float det = a*A + b*Bc + c*Cc;
    float id = 1.0f / det;
    float* Ki = g_Kinv + n*9;
    Ki[0] = A*id;             Ki[1] = (c*h - b*i)*id;  Ki[2] = (b*f - c*e)*id;
    Ki[3] = Bc*id;            Ki[4] = (a*i - c*g)*id;  Ki[5] = (c*d - a*f)*id;
    Ki[6] = Cc*id;            Ki[7] = (b*g - a*h)*id;  Ki[8] = (a*e - b*d)*id;

    const float* Ep = extr + n*16;  // b = 0, 4x4 row-major
    float* Rm = g_Rm + n*9;
    float* tv = g_tv + n*3;
    #pragma unroll
    for (int r = 0; r < 3; r++) {
        #pragma unroll
        for (int cc = 0; cc < 3; cc++) Rm[r*3+cc] = Ep[r*4+cc];
        tv[r] = Ep[r*4+3];
    }
}

// ---------------------------------------------------------------------------
// feat (B,N,C,H,W) -> g_featT (B,N,H,W,C): makes per-point channel rows
// contiguous (512B) so the scatter's loads and vector REDs are coalesced.
// ---------------------------------------------------------------------------
__global__ void transpose_feat(const float* __restrict__ feat) {
    int pix = blockIdx.x;            // 0 .. B*NCAM*HW-1
    int c   = threadIdx.x;           // 0 .. 127
    int hw  = pix % HW;
    int bn  = pix / HW;
    g_featT[(size_t)pix*CH + c] = feat[((size_t)bn*CH + c)*HW + hw];
}

// ---------------------------------------------------------------------------
// Scatter: one WARP per geometry point. Geometry computed redundantly per
// lane (cheap, no divergence: whole warp shares validity). Lane l handles
// channels [4l, 4l+4) for both batches via red.global.add.v4.f32.
// ---------------------------------------------------------------------------
__global__ void scatter_kernel(const float* __restrict__ depth) {
    int gid  = blockIdx.x * blockDim.x + threadIdx.x;
    int wp   = gid >> 5;
    if (wp >= NPTS) return;
    int lane = gid & 31;

    // decode: point index within (n): p = (dci*IH + h)*IW + w
    int w   = wp % IW;  int t = wp / IW;
    int h   = t % IH;   t /= IH;
    int dci = t % ND;
    int n   = t / ND;

    float dd = 1.0f + (59.0f / 63.0f) * (float)dci;  // linspace(1,60,64)
    float ux = (float)w * dd;
    float vy = (float)h * dd;

    const float* Ki = g_Kinv + n*9;
    float pcx = Ki[0]*ux + Ki[1]*vy + Ki[2]*dd;
    float pcy = Ki[3]*ux + Ki[4]*vy + Ki[5]*dd;
    float pcz = Ki[6]*ux + Ki[7]*vy + Ki[8]*dd;

    const float* Rm = g_Rm + n*9;
    const float* tv = g_tv + n*3;
    float px = Rm[0]*pcx + Rm[1]*pcy + Rm[2]*pcz + tv[0];
    float py = Rm[3]*pcx + Rm[4]*pcy + Rm[5]*pcz + tv[1];
    float pz = Rm[6]*pcx + Rm[7]*pcy + Rm[8]*pcz + tv[2];

    // Match reference: float division, then C-style truncation cast,
    // range checks on the post-cast int (so [-51.6,-51.2) -> bin 0 is valid).
    int xi = (int)__fdiv_rn(px - (-51.2f), 0.4f);
    int yi = (int)__fdiv_rn(py - (-51.2f), 0.4f);
    bool valid = (xi >= 0) & (xi < BEV_W) & (yi >= 0) & (yi < BEV_H)
               & (pz >= -5.0f) & (pz <= 3.0f);
    if (!valid) return;

    int bin = yi * BEV_W + xi;
    if (lane == 0) atomicAdd(&g_cnt[bin], 1.0f);   // geometry-only count

    int pixbase = h*IW + w;
    #pragma unroll
    for (int b = 0; b < BATCH; b++) {
        int bn = b*NCAM + n;
        float dp = depth[((size_t)bn*ND + dci)*HW + pixbase];
        const float4* fp = (const float4*)(g_featT + ((size_t)bn*HW + pixbase)*CH) + lane;
        float4 f = *fp;
        float* dst = g_scratch + ((size_t)b*NBIN + bin)*CH + lane*4;
        asm volatile("red.global.add.v4.f32 [%0], {%1,%2,%3,%4};"
                     :: "l"(dst), "f"(f.x*dp), "f"(f.y*dp), "f"(f.z*dp), "f"(f.w*dp)
                     : "memory");
    }
}

// ---------------------------------------------------------------------------
// Finalize: transpose (b, bin, c) -> (b, c, bin) through a padded shared tile
// fused with the count-normalization. Writes every element of d_out.
// ---------------------------------------------------------------------------
__global__ void finalize_kernel(float* __restrict__ out) {
    __shared__ float tile[32][CH + 1];   // 32 bins x 128 channels, padded
    int b    = blockIdx.y;
    int bin0 = blockIdx.x * 32;
    int tx = threadIdx.x;   // 0..31
    int ty = threadIdx.y;   // 0..31

    const float* src = g_scratch + ((size_t)b*NBIN + bin0)*CH;
    #pragma unroll
    for (int k = 0; k < 4; k++)
        tile[ty][tx + 32*k] = src[(size_t)ty*CH + tx + 32*k];
    __syncthreads();

    float cnt = g_cnt[bin0 + tx] + 1e-5f;
    #pragma unroll
    for (int k = 0; k < 4; k++) {
        int c = ty + 32*k;
        out[((size_t)b*CH + c)*NBIN + bin0 + tx] = __fdiv_rn(tile[tx][c], cnt);
    }
}

extern "C" void kernel_launch(void* const* d_in, const int* in_sizes, int n_in,
                              void* d_out, int out_size) {
    const float* feat  = (const float*)d_in[0];
    const float* depth = (const float*)d_in[1];
    const float* intr  = (const float*)d_in[2];
    const float* extr  = (const float*)d_in[3];
    const int*   img_h = (const int*)d_in[4];
    const int*   img_w = (const int*)d_in[5];
    float* out = (float*)d_out;

    void *scratch_ptr, *cnt_ptr;
    cudaGetSymbolAddress(&scratch_ptr, g_scratch);
    cudaGetSymbolAddress(&cnt_ptr, g_cnt);
    cudaMemsetAsync(scratch_ptr, 0, sizeof(float)*(size_t)BATCH*NBIN*CH);
    cudaMemsetAsync(cnt_ptr, 0, sizeof(float)*NBIN);

    setup_kernel<<<1, 32>>>(intr, extr, img_h, img_w);
    transpose_feat<<<BATCH*NCAM*HW, CH>>>(feat);
    scatter_kernel<<<(NPTS*32 + 255)/256, 256>>>(depth);
    finalize_kernel<<<dim3(NBIN/32, BATCH), dim3(32, 32)>>>(out);
}